// round 6
// baseline (speedup 1.0000x reference)
#include <cuda_runtime.h>

// ---------------------------------------------------------------------------
// 3-layer GRU + linear head. B=64, T=512, F=128, H=512, 3H=1536, O=128.
// ---------------------------------------------------------------------------
#define B_SZ   64
#define T_SZ   512
#define F_SZ   128
#define H_SZ   512
#define G3_SZ  1536
#define O_SZ   128
#define M_SZ   (B_SZ * T_SZ)

#define SCAN_NBLK  128
#define GRP_BLKS   32

typedef unsigned long long u64;

__device__ __forceinline__ u64 splat2(float x) {
    u64 r; asm("mov.b64 %0, {%1, %1};" : "=l"(r) : "f"(x)); return r;
}
__device__ __forceinline__ void fma2(u64 &d, u64 a, u64 b) {
    asm("fma.rn.f32x2 %0, %1, %2, %0;" : "+l"(d) : "l"(a), "l"(b));
}
__device__ __forceinline__ float2 unpack2(u64 v) {
    float2 f; asm("mov.b64 {%0, %1}, %2;" : "=f"(f.x), "=f"(f.y) : "l"(v)); return f;
}
__device__ __forceinline__ unsigned ld_acq(const unsigned* p) {
    unsigned v; asm volatile("ld.global.acquire.gpu.u32 %0, [%1];" : "=r"(v) : "l"(p) : "memory"); return v;
}
__device__ __forceinline__ void st_rel(unsigned* p, unsigned v) {
    asm volatile("st.global.release.gpu.u32 [%0], %1;" :: "l"(p), "r"(v) : "memory");
}

// ---------------------------------------------------------------------------
// Scratch (device globals -- allocation-free per harness rules)
// ---------------------------------------------------------------------------
__device__ float    g_xp[(size_t)M_SZ * G3_SZ];
__device__ float    g_hseq[(size_t)M_SZ * H_SZ];
__device__ unsigned g_flags[4][32];   // per-block step counters; one 128B line/group

// ---------------------------------------------------------------------------
// GEMM: C[M,N] = A[M,K] @ W[N,K]^T + bias[N].  128x128x16 tile, f32x2 FMA,
// register double-buffered gmem loads.  (unchanged from R5)
// ---------------------------------------------------------------------------
__global__ void __launch_bounds__(256)
gemm_bias_kernel(const float* __restrict__ A, const float* __restrict__ W,
                 const float* __restrict__ bias, float* __restrict__ C,
                 int M, int N, int K)
{
    __shared__ float As[16][132];
    __shared__ float Ws[16][132];

    const int tid = threadIdx.x;
    const int tx  = tid & 15;
    const int ty  = tid >> 4;
    const int m0  = blockIdx.y * 128;
    const int n0  = blockIdx.x * 128;

    u64 acc[8][4];
#pragma unroll
    for (int i = 0; i < 8; i++)
#pragma unroll
        for (int j = 0; j < 4; j++) acc[i][j] = 0ull;

    const int lr = tid >> 2;
    const int lk = (tid & 3) * 4;

    float4 pa[2], pw[2];
#pragma unroll
    for (int h = 0; h < 2; h++) {
        const int row = lr + h * 64;
        pa[h] = *(const float4*)(A + (size_t)(m0 + row) * K + lk);
        pw[h] = *(const float4*)(W + (size_t)(n0 + row) * K + lk);
    }

    for (int k0 = 0; k0 < K; k0 += 16) {
#pragma unroll
        for (int h = 0; h < 2; h++) {
            const int row = lr + h * 64;
            As[lk + 0][row] = pa[h].x; As[lk + 1][row] = pa[h].y;
            As[lk + 2][row] = pa[h].z; As[lk + 3][row] = pa[h].w;
            Ws[lk + 0][row] = pw[h].x; Ws[lk + 1][row] = pw[h].y;
            Ws[lk + 2][row] = pw[h].z; Ws[lk + 3][row] = pw[h].w;
        }
        __syncthreads();
        if (k0 + 16 < K) {
#pragma unroll
            for (int h = 0; h < 2; h++) {
                const int row = lr + h * 64;
                pa[h] = *(const float4*)(A + (size_t)(m0 + row) * K + k0 + 16 + lk);
                pw[h] = *(const float4*)(W + (size_t)(n0 + row) * K + k0 + 16 + lk);
            }
        }
#pragma unroll
        for (int k = 0; k < 16; k++) {
            float4 a0 = *(const float4*)&As[k][ty * 8];
            float4 a1 = *(const float4*)&As[k][ty * 8 + 4];
            ulonglong2 w01 = *(const ulonglong2*)&Ws[k][tx * 8];
            ulonglong2 w23 = *(const ulonglong2*)&Ws[k][tx * 8 + 4];
            float av[8] = {a0.x, a0.y, a0.z, a0.w, a1.x, a1.y, a1.z, a1.w};
#pragma unroll
            for (int i = 0; i < 8; i++) {
                u64 as = splat2(av[i]);
                fma2(acc[i][0], as, w01.x);
                fma2(acc[i][1], as, w01.y);
                fma2(acc[i][2], as, w23.x);
                fma2(acc[i][3], as, w23.y);
            }
        }
        __syncthreads();
    }

#pragma unroll
    for (int i = 0; i < 8; i++) {
        const int m = m0 + ty * 8 + i;
        float* crow = C + (size_t)m * N + n0 + tx * 8;
#pragma unroll
        for (int j = 0; j < 4; j++) {
            float2 v = unpack2(acc[i][j]);
            const int n = n0 + tx * 8 + j * 2;
            crow[j * 2 + 0] = v.x + bias[n + 0];
            crow[j * 2 + 1] = v.y + bias[n + 1];
        }
    }
}

// ---------------------------------------------------------------------------
// Persistent GRU scan. 128 blocks = 4 batch-groups x 32 j-tiles, 512 threads.
// jg = tid&7 (j pair), bg = (tid>>3)&3 (batch quad), ks = tid>>5 (warp id,
// k-split 16, 32 k's each). Micro-tile: 4b x 2j x 3g packed f32x2.
// NEW: warp-local h staging (warp ks stages only cols [ks*32, ks*32+32) and
// flows straight into its dot via __syncwarp), and a one-hop group barrier
// (warp 0 polls all 32 flags in one cache line, bar.sync releases the block).
// ---------------------------------------------------------------------------
struct ScanSmem {
    float    ws[3][8][1028];   // [gate][jpair][k*2+p]
    float    hs[16][516];      // h_{t-1} tile
    float    red[512][26];     // 24 partials per thread, pitch 26 (2-way max)
    float    bhs[48];
    unsigned baseu;
};

__global__ void __launch_bounds__(512, 1)
scan_kernel(const float* __restrict__ Whh, const float* __restrict__ bhh,
            const float* __restrict__ xp, float* __restrict__ hseq)
{
    extern __shared__ ScanSmem smem[];
    ScanSmem& s = smem[0];

    const int tid  = threadIdx.x;
    const int lane = tid & 31;
    const int jg   = tid & 7;
    const int bg   = (tid >> 3) & 3;
    const int ks   = tid >> 5;          // warp id
    const int bt   = blockIdx.x >> 5;
    const int jt   = blockIdx.x & 31;
    const int b0   = bt * 16;
    const int j0   = jt * 16;

    if (tid == 0) s.baseu = ld_acq(&g_flags[bt][jt]);   // own flag = launch base

    // Resident weights: 48 rows x 512, pair-interleaved over j.
    for (int i = tid; i < 48 * 128; i += 512) {
        const int rl = i >> 7, k4 = i & 127;
        const int gg = rl >> 4, jj = rl & 15;
        float4 v = *(const float4*)(Whh + (size_t)(gg * H_SZ + j0 + jj) * H_SZ + k4 * 4);
        const int jp = jj >> 1, p = jj & 1;
        float* w = &s.ws[gg][jp][0];
        w[(k4 * 4 + 0) * 2 + p] = v.x;
        w[(k4 * 4 + 1) * 2 + p] = v.y;
        w[(k4 * 4 + 2) * 2 + p] = v.z;
        w[(k4 * 4 + 3) * 2 + p] = v.w;
    }
    if (tid < 48) s.bhs[tid] = bhh[(tid >> 4) * H_SZ + j0 + (tid & 15)];
    __syncthreads();

    const unsigned base_flag = s.baseu;

    // Staging geometry for this lane (within its warp's 32-col slice).
    const int st_row = lane >> 3;             // + 4u, u = 0..3
    const int st_col = ks * 32 + (lane & 7) * 4;

    // Finalizer identity (tid < 128): 1 batch x 2 j each.
    const int fb   = tid >> 5;
    const int fi5  = tid & 31;
    const int fbg  = fi5 >> 3;
    const int fjg  = fi5 & 7;
    const int fbl  = fbg * 4 + fb;
    const int fjl0 = fjg * 2;

    // xp prefetch for t = 0
    float2 xv[3];
    if (tid < 128) {
        const size_t row = ((size_t)(b0 + fbl) * T_SZ + 0) * G3_SZ;
#pragma unroll
        for (int g = 0; g < 3; g++)
            xv[g] = *(const float2*)(xp + row + g * H_SZ + j0 + fjl0);
    }

    for (int t = 0; t < T_SZ; t++) {
        // ---- warp-local h staging (no block sync before the dot)
        if (t == 0) {
            const float4 z = make_float4(0.f, 0.f, 0.f, 0.f);
#pragma unroll
            for (int u = 0; u < 4; u++)
                *(float4*)&s.hs[st_row + 4 * u][st_col] = z;
        } else {
            float4 v[4];
#pragma unroll
            for (int u = 0; u < 4; u++)
                v[u] = *(const float4*)(hseq +
                        ((size_t)(b0 + st_row + 4 * u) * T_SZ + (t - 1)) * H_SZ + st_col);
#pragma unroll
            for (int u = 0; u < 4; u++)
                *(float4*)&s.hs[st_row + 4 * u][st_col] = v[u];
        }
        __syncwarp();

        // ---- partial dots: 4b x 2j x 3g over this warp's 32 k's
        u64 acc[4][3];
#pragma unroll
        for (int b = 0; b < 4; b++)
#pragma unroll
            for (int g = 0; g < 3; g++) acc[b][g] = 0ull;

        {
            const float* wr = &s.ws[0][jg][ks * 64];
            const float* wz = &s.ws[1][jg][ks * 64];
            const float* wn = &s.ws[2][jg][ks * 64];
            const float* hb = &s.hs[bg * 4][ks * 32];
#pragma unroll 2
            for (int c = 0; c < 8; c++) {
                ulonglong2 rA = *(const ulonglong2*)(wr + c * 8);
                ulonglong2 rB = *(const ulonglong2*)(wr + c * 8 + 4);
                ulonglong2 zA = *(const ulonglong2*)(wz + c * 8);
                ulonglong2 zB = *(const ulonglong2*)(wz + c * 8 + 4);
                ulonglong2 nA = *(const ulonglong2*)(wn + c * 8);
                ulonglong2 nB = *(const ulonglong2*)(wn + c * 8 + 4);
#pragma unroll
                for (int b = 0; b < 4; b++) {
                    float4 h = *(const float4*)(hb + b * 516 + c * 4);
                    u64 a0 = splat2(h.x), a1 = splat2(h.y);
                    u64 a2 = splat2(h.z), a3 = splat2(h.w);
                    fma2(acc[b][0], a0, rA.x); fma2(acc[b][0], a1, rA.y);
                    fma2(acc[b][0], a2, rB.x); fma2(acc[b][0], a3, rB.y);
                    fma2(acc[b][1], a0, zA.x); fma2(acc[b][1], a1, zA.y);
                    fma2(acc[b][1], a2, zB.x); fma2(acc[b][1], a3, zB.y);
                    fma2(acc[b][2], a0, nA.x); fma2(acc[b][2], a1, nA.y);
                    fma2(acc[b][2], a2, nB.x); fma2(acc[b][2], a3, nB.y);
                }
            }
        }

        // ---- write partials: [b][g][p] order, 12 x STS.64
        {
            float* rp = &s.red[tid][0];
#pragma unroll
            for (int b = 0; b < 4; b++)
#pragma unroll
                for (int g = 0; g < 3; g++)
                    *(float2*)(rp + b * 6 + g * 2) = unpack2(acc[b][g]);
        }
        __syncthreads();

        // ---- finalize: tid < 128, each 1 batch x 2 j; sum 16 k-slices
        if (tid < 128) {
            float2 t0 = make_float2(0.f, 0.f), t1 = t0, t2 = t0;
#pragma unroll
            for (int sdx = 0; sdx < 16; sdx++) {
                const float* rp = &s.red[sdx * 32 + fi5][fb * 6];
                float2 a = *(const float2*)(rp + 0);
                float2 b = *(const float2*)(rp + 2);
                float2 c = *(const float2*)(rp + 4);
                t0.x += a.x; t0.y += a.y;
                t1.x += b.x; t1.y += b.y;
                t2.x += c.x; t2.y += c.y;
            }
            float2 hv;
#pragma unroll
            for (int p = 0; p < 2; p++) {
                const int jl = fjl0 + p;
                float dr = (p == 0) ? t0.x : t0.y;
                float dz = (p == 0) ? t1.x : t1.y;
                float dn = (p == 0) ? t2.x : t2.y;
                float xr = (p == 0) ? xv[0].x : xv[0].y;
                float xz = (p == 0) ? xv[1].x : xv[1].y;
                float xn = (p == 0) ? xv[2].x : xv[2].y;
                float rg = 1.f / (1.f + __expf(-(xr + dr + s.bhs[jl])));
                float zg = 1.f / (1.f + __expf(-(xz + dz + s.bhs[16 + jl])));
                float ng = tanhf(xn + rg * (dn + s.bhs[32 + jl]));
                float hp = s.hs[fbl][j0 + jl];
                float h  = (1.f - zg) * ng + zg * hp;
                if (p == 0) hv.x = h; else hv.y = h;
            }
            *(float2*)(hseq + ((size_t)(b0 + fbl) * T_SZ + t) * H_SZ + j0 + fjl0) = hv;

            // prefetch xp for next step (overlaps the barrier)
            const int tn = (t + 1 < T_SZ) ? t + 1 : t;
            const size_t row = ((size_t)(b0 + fbl) * T_SZ + tn) * G3_SZ;
#pragma unroll
            for (int g = 0; g < 3; g++)
                xv[g] = *(const float2*)(xp + row + g * H_SZ + j0 + fjl0);
        }
        __syncthreads();   // finalize STGs + hs reads complete block-wide

        // ---- one-hop group barrier
        {
            const unsigned nxt = base_flag + (unsigned)t + 1u;
            if (tid == 0) st_rel(&g_flags[bt][jt], nxt);
            if (t + 1 < T_SZ) {
                if (tid < 32) {      // warp 0: one lane per group flag (same line)
                    while ((int)(ld_acq(&g_flags[bt][lane]) - nxt) < 0) { }
                }
                __syncthreads();     // release block once all 32 flags reached t+1
            }
        }
    }
}

// ---------------------------------------------------------------------------
// Launch
// ---------------------------------------------------------------------------
extern "C" void kernel_launch(void* const* d_in, const int* in_sizes, int n_in,
                              void* d_out, int out_size)
{
    (void)in_sizes; (void)n_in; (void)out_size;
    const float* x    = (const float*)d_in[0];
    const float* Wih0 = (const float*)d_in[1];
    const float* Whh0 = (const float*)d_in[2];
    const float* bih0 = (const float*)d_in[3];
    const float* bhh0 = (const float*)d_in[4];
    const float* Wih1 = (const float*)d_in[5];
    const float* Whh1 = (const float*)d_in[6];
    const float* bih1 = (const float*)d_in[7];
    const float* bhh1 = (const float*)d_in[8];
    const float* Wih2 = (const float*)d_in[9];
    const float* Whh2 = (const float*)d_in[10];
    const float* bih2 = (const float*)d_in[11];
    const float* bhh2 = (const float*)d_in[12];
    const float* Wout = (const float*)d_in[13];
    const float* bout = (const float*)d_in[14];
    float* out = (float*)d_out;

    cudaFuncSetAttribute(scan_kernel, cudaFuncAttributeMaxDynamicSharedMemorySize,
                         (int)sizeof(ScanSmem));

    void *xp_v = nullptr, *hs_v = nullptr;
    cudaGetSymbolAddress(&xp_v, g_xp);
    cudaGetSymbolAddress(&hs_v, g_hseq);
    float* xpd = (float*)xp_v;
    float* hs  = (float*)hs_v;

    const dim3 gblk(256), sblk(512);
    const dim3 g_proj(G3_SZ / 128, M_SZ / 128);
    const dim3 g_head(O_SZ / 128,  M_SZ / 128);
    const size_t scan_smem = sizeof(ScanSmem);

    gemm_bias_kernel<<<g_proj, gblk>>>(x,  Wih0, bih0, xpd, M_SZ, G3_SZ, F_SZ);
    scan_kernel<<<SCAN_NBLK, sblk, scan_smem>>>(Whh0, bhh0, xpd, hs);
    gemm_bias_kernel<<<g_proj, gblk>>>(hs, Wih1, bih1, xpd, M_SZ, G3_SZ, H_SZ);
    scan_kernel<<<SCAN_NBLK, sblk, scan_smem>>>(Whh1, bhh1, xpd, hs);
    gemm_bias_kernel<<<g_proj, gblk>>>(hs, Wih2, bih2, xpd, M_SZ, G3_SZ, H_SZ);
    scan_kernel<<<SCAN_NBLK, sblk, scan_smem>>>(Whh2, bhh2, xpd, hs);
    gemm_bias_kernel<<<g_head, gblk>>>(hs, Wout, bout, out, M_SZ, O_SZ, H_SZ);
}

// round 7
// speedup vs baseline: 1.1339x; 1.1339x over previous
#include <cuda_runtime.h>

// ---------------------------------------------------------------------------
// 3-layer GRU + linear head. B=64, T=512, F=128, H=512, 3H=1536, O=128.
// ---------------------------------------------------------------------------
#define B_SZ   64
#define T_SZ   512
#define F_SZ   128
#define H_SZ   512
#define G3_SZ  1536
#define O_SZ   128
#define M_SZ   (B_SZ * T_SZ)

#define SCAN_NBLK  128

typedef unsigned long long u64;

__device__ __forceinline__ u64 splat2(float x) {
    u64 r; asm("mov.b64 %0, {%1, %1};" : "=l"(r) : "f"(x)); return r;
}
__device__ __forceinline__ void fma2(u64 &d, u64 a, u64 b) {
    asm("fma.rn.f32x2 %0, %1, %2, %0;" : "+l"(d) : "l"(a), "l"(b));
}
__device__ __forceinline__ float2 unpack2(u64 v) {
    float2 f; asm("mov.b64 {%0, %1}, %2;" : "=f"(f.x), "=f"(f.y) : "l"(v)); return f;
}
__device__ __forceinline__ unsigned ld_acq(const unsigned* p) {
    unsigned v; asm volatile("ld.global.acquire.gpu.u32 %0, [%1];" : "=r"(v) : "l"(p) : "memory"); return v;
}
__device__ __forceinline__ void st_rel(unsigned* p, unsigned v) {
    asm volatile("st.global.release.gpu.u32 [%0], %1;" :: "l"(p), "r"(v) : "memory");
}

// ---------------------------------------------------------------------------
// Scratch (device globals -- allocation-free per harness rules)
// ---------------------------------------------------------------------------
__device__ float    g_xp[(size_t)M_SZ * G3_SZ];
__device__ float    g_hseq[(size_t)M_SZ * H_SZ];
__device__ unsigned g_flags[4][32];   // per-block step counters; one line per group
__device__ unsigned g_genf[4][32];    // generation per group at [g][0]

// ---------------------------------------------------------------------------
// GEMM: C[M,N] = A[M,K] @ W[N,K]^T + bias[N].  128x128x16 tile, f32x2 FMA,
// smem ping-pong double buffering (one __syncthreads per K-16 iteration).
// ---------------------------------------------------------------------------
__global__ void __launch_bounds__(256)
gemm_bias_kernel(const float* __restrict__ A, const float* __restrict__ W,
                 const float* __restrict__ bias, float* __restrict__ C,
                 int M, int N, int K)
{
    __shared__ float As[2][16][132];
    __shared__ float Ws[2][16][132];

    const int tid = threadIdx.x;
    const int tx  = tid & 15;
    const int ty  = tid >> 4;
    const int m0  = blockIdx.y * 128;
    const int n0  = blockIdx.x * 128;

    u64 acc[8][4];
#pragma unroll
    for (int i = 0; i < 8; i++)
#pragma unroll
        for (int j = 0; j < 4; j++) acc[i][j] = 0ull;

    const int lr = tid >> 2;
    const int lk = (tid & 3) * 4;
    const int nIter = K >> 4;

    float4 pa[2], pw[2];
#pragma unroll
    for (int h = 0; h < 2; h++) {
        const int row = lr + h * 64;
        pa[h] = *(const float4*)(A + (size_t)(m0 + row) * K + lk);
        pw[h] = *(const float4*)(W + (size_t)(n0 + row) * K + lk);
    }
#pragma unroll
    for (int h = 0; h < 2; h++) {
        const int row = lr + h * 64;
        As[0][lk + 0][row] = pa[h].x; As[0][lk + 1][row] = pa[h].y;
        As[0][lk + 2][row] = pa[h].z; As[0][lk + 3][row] = pa[h].w;
        Ws[0][lk + 0][row] = pw[h].x; Ws[0][lk + 1][row] = pw[h].y;
        Ws[0][lk + 2][row] = pw[h].z; Ws[0][lk + 3][row] = pw[h].w;
    }
    __syncthreads();

    for (int it = 0; it < nIter; it++) {
        const int buf = it & 1;
        if (it + 1 < nIter) {
#pragma unroll
            for (int h = 0; h < 2; h++) {
                const int row = lr + h * 64;
                pa[h] = *(const float4*)(A + (size_t)(m0 + row) * K + (it + 1) * 16 + lk);
                pw[h] = *(const float4*)(W + (size_t)(n0 + row) * K + (it + 1) * 16 + lk);
            }
        }
#pragma unroll
        for (int k = 0; k < 16; k++) {
            float4 a0 = *(const float4*)&As[buf][k][ty * 8];
            float4 a1 = *(const float4*)&As[buf][k][ty * 8 + 4];
            ulonglong2 w01 = *(const ulonglong2*)&Ws[buf][k][tx * 8];
            ulonglong2 w23 = *(const ulonglong2*)&Ws[buf][k][tx * 8 + 4];
            float av[8] = {a0.x, a0.y, a0.z, a0.w, a1.x, a1.y, a1.z, a1.w};
#pragma unroll
            for (int i = 0; i < 8; i++) {
                u64 as = splat2(av[i]);
                fma2(acc[i][0], as, w01.x);
                fma2(acc[i][1], as, w01.y);
                fma2(acc[i][2], as, w23.x);
                fma2(acc[i][3], as, w23.y);
            }
        }
        if (it + 1 < nIter) {
            const int nb = buf ^ 1;
#pragma unroll
            for (int h = 0; h < 2; h++) {
                const int row = lr + h * 64;
                As[nb][lk + 0][row] = pa[h].x; As[nb][lk + 1][row] = pa[h].y;
                As[nb][lk + 2][row] = pa[h].z; As[nb][lk + 3][row] = pa[h].w;
                Ws[nb][lk + 0][row] = pw[h].x; Ws[nb][lk + 1][row] = pw[h].y;
                Ws[nb][lk + 2][row] = pw[h].z; Ws[nb][lk + 3][row] = pw[h].w;
            }
            __syncthreads();
        }
    }

#pragma unroll
    for (int i = 0; i < 8; i++) {
        const int m = m0 + ty * 8 + i;
        float* crow = C + (size_t)m * N + n0 + tx * 8;
#pragma unroll
        for (int j = 0; j < 4; j++) {
            float2 v = unpack2(acc[i][j]);
            const int n = n0 + tx * 8 + j * 2;
            crow[j * 2 + 0] = v.x + bias[n + 0];
            crow[j * 2 + 1] = v.y + bias[n + 1];
        }
    }
}

// ---------------------------------------------------------------------------
// Persistent GRU scan. 128 blocks = 4 batch-groups x 32 j-tiles, 512 threads.
// jg = tid&7 (j pair), bg = (tid>>3)&3 (batch quad), ks = tid>>5 (warp id,
// k-split 16, 32 k's each). Micro-tile: 4b x 2j x 3g packed f32x2.
// Warp-local h staging (warp ks stages exactly the 32 columns its dot reads).
// Two-phase finalize: 384 threads reduce k-slices, 128 threads apply gates.
// Barrier: R5 two-hop (leader warp polls 32 flags; others spin one gen word).
// ---------------------------------------------------------------------------
struct ScanSmem {
    float    ws[3][8][1028];   // [gate][jpair][k*2+p]
    float    hs[16][516];      // h_{t-1} tile
    float    red[512][26];     // 24 partials per thread, pitch 26
    float    fin[768];         // 384 float2 reduced totals
    float    bhs[48];
    unsigned baseu[2];
};

__global__ void __launch_bounds__(512, 1)
scan_kernel(const float* __restrict__ Whh, const float* __restrict__ bhh,
            const float* __restrict__ xp, float* __restrict__ hseq)
{
    extern __shared__ ScanSmem smem[];
    ScanSmem& s = smem[0];

    const int tid  = threadIdx.x;
    const int lane = tid & 31;
    const int jg   = tid & 7;
    const int bg   = (tid >> 3) & 3;
    const int ks   = tid >> 5;          // warp id
    const int bt   = blockIdx.x >> 5;
    const int jt   = blockIdx.x & 31;
    const int b0   = bt * 16;
    const int j0   = jt * 16;

    if (tid == 0) {
        s.baseu[0] = ld_acq(&g_flags[bt][jt]);
        s.baseu[1] = ld_acq(&g_genf[bt][0]);
    }

    // Resident weights: 48 rows x 512, pair-interleaved over j.
    for (int i = tid; i < 48 * 128; i += 512) {
        const int rl = i >> 7, k4 = i & 127;
        const int gg = rl >> 4, jj = rl & 15;
        float4 v = *(const float4*)(Whh + (size_t)(gg * H_SZ + j0 + jj) * H_SZ + k4 * 4);
        const int jp = jj >> 1, p = jj & 1;
        float* w = &s.ws[gg][jp][0];
        w[(k4 * 4 + 0) * 2 + p] = v.x;
        w[(k4 * 4 + 1) * 2 + p] = v.y;
        w[(k4 * 4 + 2) * 2 + p] = v.z;
        w[(k4 * 4 + 3) * 2 + p] = v.w;
    }
    if (tid < 48) s.bhs[tid] = bhh[(tid >> 4) * H_SZ + j0 + (tid & 15)];
    __syncthreads();

    const unsigned base_flag = s.baseu[0];
    const unsigned base_gen  = s.baseu[1];

    // Warp-local staging geometry (within this warp's 32-col k-slice).
    const int st_row = lane >> 3;
    const int st_col = ks * 32 + (lane & 7) * 4;

    // Phase-A identity (tid < 384): one (b, gate) float2 column.
    const int fa5  = tid & 31;          // fi5
    const int rest = tid >> 5;          // fb*3 + g  (0..11)
    const int fba  = rest / 3;
    const int ga   = rest - fba * 3;

    // Phase-B identity (tid < 128): 1 batch x 2 j each.
    const int fb   = tid >> 5;
    const int fi5  = tid & 31;
    const int fbg  = fi5 >> 3;
    const int fjg  = fi5 & 7;
    const int fbl  = fbg * 4 + fb;
    const int fjl0 = fjg * 2;

    // xp prefetch for t = 0
    float2 xv[3];
    if (tid < 128) {
        const size_t row = ((size_t)(b0 + fbl) * T_SZ + 0) * G3_SZ;
#pragma unroll
        for (int g = 0; g < 3; g++)
            xv[g] = *(const float2*)(xp + row + g * H_SZ + j0 + fjl0);
    }

    for (int t = 0; t < T_SZ; t++) {
        // ---- warp-local h staging (no block sync before the dot)
        if (t == 0) {
            const float4 z = make_float4(0.f, 0.f, 0.f, 0.f);
#pragma unroll
            for (int u = 0; u < 4; u++)
                *(float4*)&s.hs[st_row + 4 * u][st_col] = z;
        } else {
            float4 v[4];
#pragma unroll
            for (int u = 0; u < 4; u++)
                v[u] = *(const float4*)(hseq +
                        ((size_t)(b0 + st_row + 4 * u) * T_SZ + (t - 1)) * H_SZ + st_col);
#pragma unroll
            for (int u = 0; u < 4; u++)
                *(float4*)&s.hs[st_row + 4 * u][st_col] = v[u];
        }
        __syncwarp();

        // ---- partial dots: 4b x 2j x 3g over this warp's 32 k's
        u64 acc[4][3];
#pragma unroll
        for (int b = 0; b < 4; b++)
#pragma unroll
            for (int g = 0; g < 3; g++) acc[b][g] = 0ull;

        {
            const float* wr = &s.ws[0][jg][ks * 64];
            const float* wz = &s.ws[1][jg][ks * 64];
            const float* wn = &s.ws[2][jg][ks * 64];
            const float* hb = &s.hs[bg * 4][ks * 32];
#pragma unroll 2
            for (int c = 0; c < 8; c++) {
                ulonglong2 rA = *(const ulonglong2*)(wr + c * 8);
                ulonglong2 rB = *(const ulonglong2*)(wr + c * 8 + 4);
                ulonglong2 zA = *(const ulonglong2*)(wz + c * 8);
                ulonglong2 zB = *(const ulonglong2*)(wz + c * 8 + 4);
                ulonglong2 nA = *(const ulonglong2*)(wn + c * 8);
                ulonglong2 nB = *(const ulonglong2*)(wn + c * 8 + 4);
#pragma unroll
                for (int b = 0; b < 4; b++) {
                    float4 h = *(const float4*)(hb + b * 516 + c * 4);
                    u64 a0 = splat2(h.x), a1 = splat2(h.y);
                    u64 a2 = splat2(h.z), a3 = splat2(h.w);
                    fma2(acc[b][0], a0, rA.x); fma2(acc[b][0], a1, rA.y);
                    fma2(acc[b][0], a2, rB.x); fma2(acc[b][0], a3, rB.y);
                    fma2(acc[b][1], a0, zA.x); fma2(acc[b][1], a1, zA.y);
                    fma2(acc[b][1], a2, zB.x); fma2(acc[b][1], a3, zB.y);
                    fma2(acc[b][2], a0, nA.x); fma2(acc[b][2], a1, nA.y);
                    fma2(acc[b][2], a2, nB.x); fma2(acc[b][2], a3, nB.y);
                }
            }
        }

        // ---- write partials: [b][g][p] order, 12 x STS.64
        {
            float* rp = &s.red[tid][0];
#pragma unroll
            for (int b = 0; b < 4; b++)
#pragma unroll
                for (int g = 0; g < 3; g++)
                    *(float2*)(rp + b * 6 + g * 2) = unpack2(acc[b][g]);
        }
        __syncthreads();

        // ---- phase A: 384 threads, each reduces one (b,g) float2 over 16 slices
        if (tid < 384) {
            const int col = fba * 6 + ga * 2;
            float2 a2 = make_float2(0.f, 0.f);
#pragma unroll
            for (int sdx = 0; sdx < 16; sdx++) {
                float2 v = *(const float2*)&s.red[sdx * 32 + fa5][col];
                a2.x += v.x; a2.y += v.y;
            }
            *(float2*)&s.fin[tid * 2] = a2;
        }
        __syncthreads();

        // ---- phase B: 128 threads apply gates, store h_t, prefetch xp(t+1)
        if (tid < 128) {
            float2 t0 = *(const float2*)&s.fin[((fb * 3 + 0) * 32 + fi5) * 2];
            float2 t1 = *(const float2*)&s.fin[((fb * 3 + 1) * 32 + fi5) * 2];
            float2 t2 = *(const float2*)&s.fin[((fb * 3 + 2) * 32 + fi5) * 2];
            float2 hv;
#pragma unroll
            for (int p = 0; p < 2; p++) {
                const int jl = fjl0 + p;
                float dr = (p == 0) ? t0.x : t0.y;
                float dz = (p == 0) ? t1.x : t1.y;
                float dn = (p == 0) ? t2.x : t2.y;
                float xr = (p == 0) ? xv[0].x : xv[0].y;
                float xz = (p == 0) ? xv[1].x : xv[1].y;
                float xn = (p == 0) ? xv[2].x : xv[2].y;
                float rg = 1.f / (1.f + __expf(-(xr + dr + s.bhs[jl])));
                float zg = 1.f / (1.f + __expf(-(xz + dz + s.bhs[16 + jl])));
                float ng = tanhf(xn + rg * (dn + s.bhs[32 + jl]));
                float hp = s.hs[fbl][j0 + jl];
                float h  = (1.f - zg) * ng + zg * hp;
                if (p == 0) hv.x = h; else hv.y = h;
            }
            *(float2*)(hseq + ((size_t)(b0 + fbl) * T_SZ + t) * H_SZ + j0 + fjl0) = hv;

            const int tn = (t + 1 < T_SZ) ? t + 1 : t;
            const size_t row = ((size_t)(b0 + fbl) * T_SZ + tn) * G3_SZ;
#pragma unroll
            for (int g = 0; g < 3; g++)
                xv[g] = *(const float2*)(xp + row + g * H_SZ + j0 + fjl0);
        }
        __syncthreads();   // h_t stores + hs reads complete block-wide

        // ---- two-hop group barrier (R5); skipped uniformly on the last step
        if (t + 1 < T_SZ) {
            const unsigned tgt = base_flag + (unsigned)t + 1u;
            if (tid == 0) st_rel(&g_flags[bt][jt], tgt);
            if (jt == 0) {
                if (tid < 32) {
                    while ((int)(ld_acq(&g_flags[bt][lane]) - tgt) < 0) { }
                    __syncwarp();
                    if (tid == 0) st_rel(&g_genf[bt][0], base_gen + (unsigned)t + 1u);
                }
            } else if (tid == 0) {
                const unsigned gt = base_gen + (unsigned)t + 1u;
                while ((int)(ld_acq(&g_genf[bt][0]) - gt) < 0) { }
            }
            __syncthreads();
        }
    }
}

// ---------------------------------------------------------------------------
// Launch
// ---------------------------------------------------------------------------
extern "C" void kernel_launch(void* const* d_in, const int* in_sizes, int n_in,
                              void* d_out, int out_size)
{
    (void)in_sizes; (void)n_in; (void)out_size;
    const float* x    = (const float*)d_in[0];
    const float* Wih0 = (const float*)d_in[1];
    const float* Whh0 = (const float*)d_in[2];
    const float* bih0 = (const float*)d_in[3];
    const float* bhh0 = (const float*)d_in[4];
    const float* Wih1 = (const float*)d_in[5];
    const float* Whh1 = (const float*)d_in[6];
    const float* bih1 = (const float*)d_in[7];
    const float* bhh1 = (const float*)d_in[8];
    const float* Wih2 = (const float*)d_in[9];
    const float* Whh2 = (const float*)d_in[10];
    const float* bih2 = (const float*)d_in[11];
    const float* bhh2 = (const float*)d_in[12];
    const float* Wout = (const float*)d_in[13];
    const float* bout = (const float*)d_in[14];
    float* out = (float*)d_out;

    cudaFuncSetAttribute(scan_kernel, cudaFuncAttributeMaxDynamicSharedMemorySize,
                         (int)sizeof(ScanSmem));

    void *xp_v = nullptr, *hs_v = nullptr;
    cudaGetSymbolAddress(&xp_v, g_xp);
    cudaGetSymbolAddress(&hs_v, g_hseq);
    float* xpd = (float*)xp_v;
    float* hs  = (float*)hs_v;

    const dim3 gblk(256), sblk(512);
    const dim3 g_proj(G3_SZ / 128, M_SZ / 128);
    const dim3 g_head(O_SZ / 128,  M_SZ / 128);
    const size_t scan_smem = sizeof(ScanSmem);

    gemm_bias_kernel<<<g_proj, gblk>>>(x,  Wih0, bih0, xpd, M_SZ, G3_SZ, F_SZ);
    scan_kernel<<<SCAN_NBLK, sblk, scan_smem>>>(Whh0, bhh0, xpd, hs);
    gemm_bias_kernel<<<g_proj, gblk>>>(hs, Wih1, bih1, xpd, M_SZ, G3_SZ, H_SZ);
    scan_kernel<<<SCAN_NBLK, sblk, scan_smem>>>(Whh1, bhh1, xpd, hs);
    gemm_bias_kernel<<<g_proj, gblk>>>(hs, Wih2, bih2, xpd, M_SZ, G3_SZ, H_SZ);
    scan_kernel<<<SCAN_NBLK, sblk, scan_smem>>>(Whh2, bhh2, xpd, hs);
    gemm_bias_kernel<<<g_head, gblk>>>(hs, Wout, bout, out, M_SZ, O_SZ, H_SZ);
}